// round 2
// baseline (speedup 1.0000x reference)
#include <cuda_runtime.h>
#include <math.h>

// Problem constants
#define BB   2
#define SS   2048
#define DD   1024
#define HH   16
#define DKH  64          // head dim
#define MTOT (BB*SS)     // 4096 rows

// -------- scratch (static device globals; allocation-free) --------
__device__ float g_qkv[(size_t)MTOT * 3 * DD];        // [4096, 3072]
__device__ float g_q  [(size_t)BB * HH * SS * DKH];   // [b,h,s,d]
__device__ float g_k  [(size_t)BB * HH * SS * DKH];
__device__ float g_v  [(size_t)BB * HH * SS * DKH];
__device__ float g_ao [(size_t)MTOT * DD];            // attention out, [b,s,h*d]

// ============================================================================
// SGEMM: C[M,N] = A[M,K] @ B[N,K]^T (+ bias[N]).  BM=BN=128, BK=8, 256 thr,
// 8x8 per-thread register tile. M,N multiples of 128; K multiple of 8.
// ============================================================================
template<bool HAS_BIAS>
__global__ __launch_bounds__(256) void sgemm_nt(
    const float* __restrict__ A, const float* __restrict__ B,
    const float* __restrict__ bias, float* __restrict__ C,
    int M, int N, int K)
{
    __shared__ float As[8][128];
    __shared__ float Bs[8][128];

    const int tid  = threadIdx.x;
    const int brow = blockIdx.y;
    const int bcol = blockIdx.x;
    const int tr   = tid / 16;        // 0..15
    const int tc   = tid % 16;        // 0..15

    const int lrow = tid >> 1;        // 0..127
    const int lcol = (tid & 1) * 4;   // 0 or 4

    const float* Aptr = A + (size_t)(brow * 128 + lrow) * K;
    const float* Bptr = B + (size_t)(bcol * 128 + lrow) * K;

    float acc[8][8];
    #pragma unroll
    for (int i = 0; i < 8; i++)
        #pragma unroll
        for (int j = 0; j < 8; j++) acc[i][j] = 0.f;

    for (int k0 = 0; k0 < K; k0 += 8) {
        float4 a = *(const float4*)(Aptr + k0 + lcol);
        float4 b = *(const float4*)(Bptr + k0 + lcol);
        As[lcol + 0][lrow] = a.x; As[lcol + 1][lrow] = a.y;
        As[lcol + 2][lrow] = a.z; As[lcol + 3][lrow] = a.w;
        Bs[lcol + 0][lrow] = b.x; Bs[lcol + 1][lrow] = b.y;
        Bs[lcol + 2][lrow] = b.z; Bs[lcol + 3][lrow] = b.w;
        __syncthreads();

        #pragma unroll
        for (int k = 0; k < 8; k++) {
            float ra[8], rb[8];
            #pragma unroll
            for (int i = 0; i < 8; i++) ra[i] = As[k][tr * 8 + i];
            #pragma unroll
            for (int j = 0; j < 8; j++) rb[j] = Bs[k][tc * 8 + j];
            #pragma unroll
            for (int i = 0; i < 8; i++)
                #pragma unroll
                for (int j = 0; j < 8; j++)
                    acc[i][j] = fmaf(ra[i], rb[j], acc[i][j]);
        }
        __syncthreads();
    }

    #pragma unroll
    for (int i = 0; i < 8; i++) {
        int row = brow * 128 + tr * 8 + i;
        float* Crow = C + (size_t)row * N + bcol * 128 + tc * 8;
        #pragma unroll
        for (int j = 0; j < 8; j++) {
            float v = acc[i][j];
            if (HAS_BIAS) v += bias[bcol * 128 + tc * 8 + j];
            Crow[j] = v;
        }
    }
}

// ============================================================================
// RoPE + split + transpose.
// qkv: [b*s, 3*1024]. Produces Q,K (rope applied) and V in [b,h,s,64] layout.
// One thread per (b,s,h,pair). Angle computed in fp32 (matching reference
// rounding), sin/cos evaluated in double (robust to fast-math).
// ============================================================================
__global__ void rope_split_kernel(const float* __restrict__ qkv,
                                  float* __restrict__ Q,
                                  float* __restrict__ K,
                                  float* __restrict__ V)
{
    int idx = blockIdx.x * blockDim.x + threadIdx.x;
    const int total = BB * SS * HH * (DKH / 2);
    if (idx >= total) return;

    int p = idx & 31;                 // pair index 0..31
    int h = (idx >> 5) & (HH - 1);
    int s = (idx >> 9) & (SS - 1);
    int b = idx >> 20;

    const float* row = qkv + (size_t)(b * SS + s) * (3 * DD);
    // inv_freq = ROPE_BASE^(-(2p)/64), ROPE_BASE = 50  (fp32, like reference)
    float inv = 1.0f / powf(50.0f, (2.0f * (float)p) / 64.0f);
    float ang = (float)s * inv;       // fp32 rounding matches reference
    double sd, cd;
    sincos((double)ang, &sd, &cd);    // accurate evaluation of the fp32 angle
    float c  = (float)cd;
    float sn = (float)sd;

    int col = h * DKH + 2 * p;
    float q0 = row[col],          q1 = row[col + 1];
    float k0 = row[DD + col],     k1 = row[DD + col + 1];
    float v0 = row[2 * DD + col], v1 = row[2 * DD + col + 1];

    size_t o = ((size_t)(b * HH + h) * SS + s) * DKH + 2 * p;
    Q[o]     = q0 * c - q1 * sn;
    Q[o + 1] = q1 * c + q0 * sn;
    K[o]     = k0 * c - k1 * sn;
    K[o + 1] = k1 * c + k0 * sn;
    V[o]     = v0;
    V[o + 1] = v1;
}

// ============================================================================
// Flash-style attention, fp32, diagonal mask, SIMPLE smem-based softmax.
// Grid: (S/64, B*H). 256 threads as 16x16.
// Per key-tile of 32:
//   Stage A: 16x16 threads compute scaled+masked scores into Sc[64][32] (smem)
//   Stage B: 64 threads, one per query row, do max/exp/sum bookkeeping serially
//   Stage C: all threads update O accumulators (rows ty*4+i, dk cols tx*4+c)
// Output written in [b, s, h*64] layout for the final GEMM.
// ============================================================================
__global__ __launch_bounds__(256) void attn_kernel(
    const float* __restrict__ Q, const float* __restrict__ K,
    const float* __restrict__ V, float* __restrict__ O)
{
    __shared__ float Qs[64][65];
    __shared__ float Ks[32][65];
    __shared__ float Vs[32][68];
    __shared__ float Sc[64][33];
    __shared__ float Mrow[64];
    __shared__ float Lrow[64];
    __shared__ float Corr[64];

    const int qt = blockIdx.x;            // query tile
    const int bh = blockIdx.y;            // b*H + h
    const int b  = bh / HH;
    const int h  = bh % HH;

    const float* Qg = Q + (size_t)bh * SS * DKH;
    const float* Kg = K + (size_t)bh * SS * DKH;
    const float* Vg = V + (size_t)bh * SS * DKH;

    const int tid = threadIdx.x;
    const int tx  = tid & 15;             // 0..15
    const int ty  = tid >> 4;             // 0..15

    // load Q tile (64 x 64), init per-row state
    for (int i = tid; i < 64 * DKH; i += 256) {
        int m = i >> 6, k = i & 63;
        Qs[m][k] = Qg[(size_t)(qt * 64 + m) * DKH + k];
    }
    if (tid < 64) { Mrow[tid] = -1e30f; Lrow[tid] = 0.f; }
    __syncthreads();

    float acc[4][4];
    #pragma unroll
    for (int i = 0; i < 4; i++)
        #pragma unroll
        for (int c = 0; c < 4; c++) acc[i][c] = 0.f;

    const float scale = 0.125f;           // 1/sqrt(64)

    for (int t = 0; t < SS / 32; ++t) {
        // load K,V tiles (32 x 64 each)
        for (int i = tid; i < 32 * DKH; i += 256) {
            int n = i >> 6, k = i & 63;
            Ks[n][k] = Kg[(size_t)(t * 32 + n) * DKH + k];
            Vs[n][k] = Vg[(size_t)(t * 32 + n) * DKH + k];
        }
        __syncthreads();

        // ---- Stage A: S = Q K^T (4x2 per thread), scale + mask, to smem ----
        float s[4][2];
        #pragma unroll
        for (int i = 0; i < 4; i++) { s[i][0] = 0.f; s[i][1] = 0.f; }
        #pragma unroll
        for (int k = 0; k < DKH; k++) {
            float qv[4], kv[2];
            #pragma unroll
            for (int i = 0; i < 4; i++) qv[i] = Qs[ty * 4 + i][k];
            kv[0] = Ks[tx * 2 + 0][k];
            kv[1] = Ks[tx * 2 + 1][k];
            #pragma unroll
            for (int i = 0; i < 4; i++) {
                s[i][0] = fmaf(qv[i], kv[0], s[i][0]);
                s[i][1] = fmaf(qv[i], kv[1], s[i][1]);
            }
        }
        #pragma unroll
        for (int i = 0; i < 4; i++) {
            int gq = qt * 64 + ty * 4 + i;
            #pragma unroll
            for (int j = 0; j < 2; j++) {
                int gk = t * 32 + tx * 2 + j;
                float v = s[i][j] * scale;
                if (gq == gk) v = -1e30f;
                Sc[ty * 4 + i][tx * 2 + j] = v;
            }
        }
        __syncthreads();

        // ---- Stage B: per-row softmax bookkeeping (1 thread per row) ----
        if (tid < 64) {
            int r = tid;
            float rmax = -1e30f;
            #pragma unroll 8
            for (int c2 = 0; c2 < 32; c2++) rmax = fmaxf(rmax, Sc[r][c2]);
            float mold = Mrow[r];
            float mnew = fmaxf(mold, rmax);
            float corr = expf(mold - mnew);
            float lsum = 0.f;
            #pragma unroll 8
            for (int c2 = 0; c2 < 32; c2++) {
                float pv = expf(Sc[r][c2] - mnew);
                Sc[r][c2] = pv;
                lsum += pv;
            }
            Mrow[r] = mnew;
            Lrow[r] = Lrow[r] * corr + lsum;
            Corr[r] = corr;
        }
        __syncthreads();

        // ---- Stage C: acc = acc*corr + P @ V ----
        #pragma unroll
        for (int i = 0; i < 4; i++) {
            float cr = Corr[ty * 4 + i];
            #pragma unroll
            for (int c = 0; c < 4; c++) acc[i][c] *= cr;
        }
        #pragma unroll 4
        for (int n = 0; n < 32; n++) {
            float pv[4], vv[4];
            #pragma unroll
            for (int i = 0; i < 4; i++) pv[i] = Sc[ty * 4 + i][n];
            #pragma unroll
            for (int c = 0; c < 4; c++) vv[c] = Vs[n][tx * 4 + c];
            #pragma unroll
            for (int i = 0; i < 4; i++)
                #pragma unroll
                for (int c = 0; c < 4; c++)
                    acc[i][c] = fmaf(pv[i], vv[c], acc[i][c]);
        }
        __syncthreads();   // before K/V/Sc overwrite next iteration
    }

    // epilogue: normalize, write [b, s, h*64 + col]
    #pragma unroll
    for (int i = 0; i < 4; i++) {
        float inv_l = 1.0f / Lrow[ty * 4 + i];
        int srow = qt * 64 + ty * 4 + i;
        float* Orow = O + ((size_t)(b * SS + srow)) * DD + h * DKH + tx * 4;
        #pragma unroll
        for (int c = 0; c < 4; c++)
            Orow[c] = acc[i][c] * inv_l;
    }
}

// ============================================================================
// launch
// ============================================================================
extern "C" void kernel_launch(void* const* d_in, const int* in_sizes, int n_in,
                              void* d_out, int out_size)
{
    // Select inputs by element count (all four sizes are distinct):
    //   x: 4,194,304   w_qkv: 3,145,728   w_out: 1,048,576   b_out: 1,024
    const float* x = nullptr; const float* w_qkv = nullptr;
    const float* w_out = nullptr; const float* b_out = nullptr;
    for (int i = 0; i < n_in; i++) {
        long n = in_sizes[i];
        if      (n == (long)MTOT * DD)     x     = (const float*)d_in[i];
        else if (n == 3L * DD * DD)        w_qkv = (const float*)d_in[i];
        else if (n == (long)DD * DD)       w_out = (const float*)d_in[i];
        else if (n == (long)DD)            b_out = (const float*)d_in[i];
    }
    float* out = (float*)d_out;

    float *qkv, *q, *k, *v, *ao;
    cudaGetSymbolAddress((void**)&qkv, g_qkv);
    cudaGetSymbolAddress((void**)&q,   g_q);
    cudaGetSymbolAddress((void**)&k,   g_k);
    cudaGetSymbolAddress((void**)&v,   g_v);
    cudaGetSymbolAddress((void**)&ao,  g_ao);

    // 1) QKV projection: [4096,1024] @ [3072,1024]^T -> [4096,3072]
    sgemm_nt<false><<<dim3((3 * DD) / 128, MTOT / 128), 256>>>(
        x, w_qkv, nullptr, qkv, MTOT, 3 * DD, DD);

    // 2) RoPE + split/transpose
    {
        int total = BB * SS * HH * (DKH / 2);
        rope_split_kernel<<<(total + 255) / 256, 256>>>(qkv, q, k, v);
    }

    // 3) attention
    attn_kernel<<<dim3(SS / 64, BB * HH), 256>>>(q, k, v, ao);

    // 4) output projection + bias: [4096,1024] @ [1024,1024]^T + b
    sgemm_nt<true><<<dim3(DD / 128, MTOT / 128), 256>>>(
        ao, w_out, b_out, out, MTOT, DD, DD);
}

// round 4
// speedup vs baseline: 1.3357x; 1.3357x over previous
#include <cuda_runtime.h>
#include <cuda_bf16.h>
#include <cstdint>
#include <math.h>

// Problem constants
#define BB   2
#define SS   2048
#define DD   1024
#define HH   16
#define DKH  64          // head dim
#define MTOT (BB*SS)     // 4096 rows

typedef __nv_bfloat16 bf16;

// -------- scratch (static device globals; allocation-free) --------
__device__ float g_qkv[(size_t)MTOT * 3 * DD];        // [4096, 3072]
__device__ float g_q  [(size_t)BB * HH * SS * DKH];   // [b,h,s,d]
__device__ float g_k  [(size_t)BB * HH * SS * DKH];
__device__ float g_v  [(size_t)BB * HH * SS * DKH];
__device__ float g_ao [(size_t)MTOT * DD];            // attention out, [b,s,h*d]

__device__ bf16 g_x_hi [(size_t)MTOT * DD];
__device__ bf16 g_x_lo [(size_t)MTOT * DD];
__device__ bf16 g_wq_hi[(size_t)3 * DD * DD];
__device__ bf16 g_wq_lo[(size_t)3 * DD * DD];
__device__ bf16 g_ao_hi[(size_t)MTOT * DD];
__device__ bf16 g_ao_lo[(size_t)MTOT * DD];
__device__ bf16 g_wo_hi[(size_t)DD * DD];
__device__ bf16 g_wo_lo[(size_t)DD * DD];

// ============================================================================
// warp mma.sync m16n8k16 bf16 (row.col), fp32 accumulate
// ============================================================================
__device__ __forceinline__ void mma16816(float* d,
                                         const uint32_t* a, const uint32_t* b) {
    asm volatile(
        "mma.sync.aligned.m16n8k16.row.col.f32.bf16.bf16.f32 "
        "{%0,%1,%2,%3}, {%4,%5,%6,%7}, {%8,%9}, {%0,%1,%2,%3};"
        : "+f"(d[0]), "+f"(d[1]), "+f"(d[2]), "+f"(d[3])
        : "r"(a[0]), "r"(a[1]), "r"(a[2]), "r"(a[3]), "r"(b[0]), "r"(b[1]));
}

// ============================================================================
// fp32 -> (hi, lo) bf16 split
// ============================================================================
__global__ void split_kernel(const float* __restrict__ src,
                             bf16* __restrict__ hi, bf16* __restrict__ lo, int n) {
    int i = blockIdx.x * blockDim.x + threadIdx.x;
    if (i >= n) return;
    float x = src[i];
    bf16 h = __float2bfloat16_rn(x);
    hi[i] = h;
    lo[i] = __float2bfloat16_rn(x - __bfloat162float(h));
}

// ============================================================================
// 3-term split-bf16 GEMM via mma.sync: C[M,N] = A[M,K] @ B[N,K]^T (+bias)
// BM=BN=128, BK=32. 256 threads = 8 warps (2x4), warp tile 64x32.
// SMEM stride 40 bf16 (80B): conflict-free fragment LDS, 16B-aligned rows.
// ============================================================================
#define GST 40   // smem row stride in bf16 elements

template<bool HAS_BIAS>
__global__ __launch_bounds__(256)
void wgemm3_kernel(const bf16* __restrict__ Ahi, const bf16* __restrict__ Alo,
                   const bf16* __restrict__ Bhi, const bf16* __restrict__ Blo,
                   const float* __restrict__ bias, float* __restrict__ C,
                   int M, int N, int K)
{
    __shared__ bf16 sAh[128][GST];
    __shared__ bf16 sAl[128][GST];
    __shared__ bf16 sBh[128][GST];
    __shared__ bf16 sBl[128][GST];

    const int tid  = threadIdx.x;
    const int wid  = tid >> 5;
    const int lane = tid & 31;
    const int lr   = lane >> 2;       // 0..7
    const int lc   = (lane & 3) * 2;  // 0,2,4,6

    const int mbase = blockIdx.y * 128;
    const int nbase = blockIdx.x * 128;
    const int wm = (wid >> 2) * 64;   // warp m offset (0 or 64)
    const int wn = (wid & 3) * 32;    // warp n offset

    float acc[4][4][4];               // [mi][ni][reg]
    #pragma unroll
    for (int mi = 0; mi < 4; mi++)
        #pragma unroll
        for (int ni = 0; ni < 4; ni++)
            #pragma unroll
            for (int r = 0; r < 4; r++) acc[mi][ni][r] = 0.f;

    for (int k0 = 0; k0 < K; k0 += 32) {
        // ---- load chunk: A/B hi+lo, 128x32 bf16 each, uint4 granules ----
        #pragma unroll
        for (int it = 0; it < 2; it++) {
            int idx = tid + it * 256;          // 0..511
            int row = idx >> 2;
            int c4  = idx & 3;                 // 16B chunk (8 bf16)
            size_t sa = (size_t)(mbase + row) * K + k0 + c4 * 8;
            size_t sb = (size_t)(nbase + row) * K + k0 + c4 * 8;
            *(uint4*)&sAh[row][c4 * 8] = *(const uint4*)(Ahi + sa);
            *(uint4*)&sAl[row][c4 * 8] = *(const uint4*)(Alo + sa);
            *(uint4*)&sBh[row][c4 * 8] = *(const uint4*)(Bhi + sb);
            *(uint4*)&sBl[row][c4 * 8] = *(const uint4*)(Blo + sb);
        }
        __syncthreads();

        #pragma unroll
        for (int ks = 0; ks < 32; ks += 16) {
            // A fragments (hi & lo)
            uint32_t ah[4][4], al[4][4];
            #pragma unroll
            for (int mi = 0; mi < 4; mi++) {
                int r0 = wm + mi * 16 + lr;
                ah[mi][0] = *(const uint32_t*)&sAh[r0    ][ks + lc];
                ah[mi][1] = *(const uint32_t*)&sAh[r0 + 8][ks + lc];
                ah[mi][2] = *(const uint32_t*)&sAh[r0    ][ks + 8 + lc];
                ah[mi][3] = *(const uint32_t*)&sAh[r0 + 8][ks + 8 + lc];
                al[mi][0] = *(const uint32_t*)&sAl[r0    ][ks + lc];
                al[mi][1] = *(const uint32_t*)&sAl[r0 + 8][ks + lc];
                al[mi][2] = *(const uint32_t*)&sAl[r0    ][ks + 8 + lc];
                al[mi][3] = *(const uint32_t*)&sAl[r0 + 8][ks + 8 + lc];
            }
            // B fragments (hi & lo)
            uint32_t bh[4][2], bl[4][2];
            #pragma unroll
            for (int ni = 0; ni < 4; ni++) {
                int rn = wn + ni * 8 + lr;
                bh[ni][0] = *(const uint32_t*)&sBh[rn][ks + lc];
                bh[ni][1] = *(const uint32_t*)&sBh[rn][ks + 8 + lc];
                bl[ni][0] = *(const uint32_t*)&sBl[rn][ks + lc];
                bl[ni][1] = *(const uint32_t*)&sBl[rn][ks + 8 + lc];
            }
            // 3-term accumulation
            #pragma unroll
            for (int mi = 0; mi < 4; mi++)
                #pragma unroll
                for (int ni = 0; ni < 4; ni++) {
                    mma16816(acc[mi][ni], ah[mi], bh[ni]);
                    mma16816(acc[mi][ni], al[mi], bh[ni]);
                    mma16816(acc[mi][ni], ah[mi], bl[ni]);
                }
        }
        __syncthreads();
    }

    // ---- epilogue ----
    #pragma unroll
    for (int mi = 0; mi < 4; mi++) {
        int row0 = mbase + wm + mi * 16 + lr;
        #pragma unroll
        for (int ni = 0; ni < 4; ni++) {
            int col0 = nbase + wn + ni * 8 + lc;
            float b0 = 0.f, b1 = 0.f;
            if (HAS_BIAS) { b0 = bias[col0]; b1 = bias[col0 + 1]; }
            float* p0 = C + (size_t)row0 * N + col0;
            float* p1 = C + (size_t)(row0 + 8) * N + col0;
            p0[0] = acc[mi][ni][0] + b0;
            p0[1] = acc[mi][ni][1] + b1;
            p1[0] = acc[mi][ni][2] + b0;
            p1[1] = acc[mi][ni][3] + b1;
        }
    }
}

// ============================================================================
// RoPE + split + transpose (unchanged, verified correct)
// ============================================================================
__global__ void rope_split_kernel(const float* __restrict__ qkv,
                                  float* __restrict__ Q,
                                  float* __restrict__ K,
                                  float* __restrict__ V)
{
    int idx = blockIdx.x * blockDim.x + threadIdx.x;
    const int total = BB * SS * HH * (DKH / 2);
    if (idx >= total) return;

    int p = idx & 31;
    int h = (idx >> 5) & (HH - 1);
    int s = (idx >> 9) & (SS - 1);
    int b = idx >> 20;

    const float* row = qkv + (size_t)(b * SS + s) * (3 * DD);
    float inv = 1.0f / powf(50.0f, (2.0f * (float)p) / 64.0f);
    float ang = (float)s * inv;
    double sd, cd;
    sincos((double)ang, &sd, &cd);
    float c  = (float)cd;
    float sn = (float)sd;

    int col = h * DKH + 2 * p;
    float q0 = row[col],          q1 = row[col + 1];
    float k0 = row[DD + col],     k1 = row[DD + col + 1];
    float v0 = row[2 * DD + col], v1 = row[2 * DD + col + 1];

    size_t o = ((size_t)(b * HH + h) * SS + s) * DKH + 2 * p;
    Q[o]     = q0 * c - q1 * sn;
    Q[o + 1] = q1 * c + q0 * sn;
    K[o]     = k0 * c - k1 * sn;
    K[o + 1] = k1 * c + k0 * sn;
    V[o]     = v0;
    V[o + 1] = v1;
}

// ============================================================================
// Flash-style attention (unchanged, verified correct)
// ============================================================================
__global__ __launch_bounds__(256) void attn_kernel(
    const float* __restrict__ Q, const float* __restrict__ K,
    const float* __restrict__ V, float* __restrict__ O)
{
    __shared__ float Qs[64][65];
    __shared__ float Ks[32][65];
    __shared__ float Vs[32][68];
    __shared__ float Sc[64][33];
    __shared__ float Mrow[64];
    __shared__ float Lrow[64];
    __shared__ float Corr[64];

    const int qt = blockIdx.x;
    const int bh = blockIdx.y;
    const int b  = bh / HH;
    const int h  = bh % HH;

    const float* Qg = Q + (size_t)bh * SS * DKH;
    const float* Kg = K + (size_t)bh * SS * DKH;
    const float* Vg = V + (size_t)bh * SS * DKH;

    const int tid = threadIdx.x;
    const int tx  = tid & 15;
    const int ty  = tid >> 4;

    for (int i = tid; i < 64 * DKH; i += 256) {
        int m = i >> 6, k = i & 63;
        Qs[m][k] = Qg[(size_t)(qt * 64 + m) * DKH + k];
    }
    if (tid < 64) { Mrow[tid] = -1e30f; Lrow[tid] = 0.f; }
    __syncthreads();

    float acc[4][4];
    #pragma unroll
    for (int i = 0; i < 4; i++)
        #pragma unroll
        for (int c = 0; c < 4; c++) acc[i][c] = 0.f;

    const float scale = 0.125f;

    for (int t = 0; t < SS / 32; ++t) {
        for (int i = tid; i < 32 * DKH; i += 256) {
            int n = i >> 6, k = i & 63;
            Ks[n][k] = Kg[(size_t)(t * 32 + n) * DKH + k];
            Vs[n][k] = Vg[(size_t)(t * 32 + n) * DKH + k];
        }
        __syncthreads();

        float s[4][2];
        #pragma unroll
        for (int i = 0; i < 4; i++) { s[i][0] = 0.f; s[i][1] = 0.f; }
        #pragma unroll
        for (int k = 0; k < DKH; k++) {
            float qv[4], kv[2];
            #pragma unroll
            for (int i = 0; i < 4; i++) qv[i] = Qs[ty * 4 + i][k];
            kv[0] = Ks[tx * 2 + 0][k];
            kv[1] = Ks[tx * 2 + 1][k];
            #pragma unroll
            for (int i = 0; i < 4; i++) {
                s[i][0] = fmaf(qv[i], kv[0], s[i][0]);
                s[i][1] = fmaf(qv[i], kv[1], s[i][1]);
            }
        }
        #pragma unroll
        for (int i = 0; i < 4; i++) {
            int gq = qt * 64 + ty * 4 + i;
            #pragma unroll
            for (int j = 0; j < 2; j++) {
                int gk = t * 32 + tx * 2 + j;
                float v = s[i][j] * scale;
                if (gq == gk) v = -1e30f;
                Sc[ty * 4 + i][tx * 2 + j] = v;
            }
        }
        __syncthreads();

        if (tid < 64) {
            int r = tid;
            float rmax = -1e30f;
            #pragma unroll 8
            for (int c2 = 0; c2 < 32; c2++) rmax = fmaxf(rmax, Sc[r][c2]);
            float mold = Mrow[r];
            float mnew = fmaxf(mold, rmax);
            float corr = expf(mold - mnew);
            float lsum = 0.f;
            #pragma unroll 8
            for (int c2 = 0; c2 < 32; c2++) {
                float pv = expf(Sc[r][c2] - mnew);
                Sc[r][c2] = pv;
                lsum += pv;
            }
            Mrow[r] = mnew;
            Lrow[r] = Lrow[r] * corr + lsum;
            Corr[r] = corr;
        }
        __syncthreads();

        #pragma unroll
        for (int i = 0; i < 4; i++) {
            float cr = Corr[ty * 4 + i];
            #pragma unroll
            for (int c = 0; c < 4; c++) acc[i][c] *= cr;
        }
        #pragma unroll 4
        for (int n = 0; n < 32; n++) {
            float pv[4], vv[4];
            #pragma unroll
            for (int i = 0; i < 4; i++) pv[i] = Sc[ty * 4 + i][n];
            #pragma unroll
            for (int c = 0; c < 4; c++) vv[c] = Vs[n][tx * 4 + c];
            #pragma unroll
            for (int i = 0; i < 4; i++)
                #pragma unroll
                for (int c = 0; c < 4; c++)
                    acc[i][c] = fmaf(pv[i], vv[c], acc[i][c]);
        }
        __syncthreads();
    }

    #pragma unroll
    for (int i = 0; i < 4; i++) {
        float inv_l = 1.0f / Lrow[ty * 4 + i];
        int srow = qt * 64 + ty * 4 + i;
        float* Orow = O + ((size_t)(b * SS + srow)) * DD + h * DKH + tx * 4;
        #pragma unroll
        for (int c = 0; c < 4; c++)
            Orow[c] = acc[i][c] * inv_l;
    }
}

// ============================================================================
// launch
// ============================================================================
extern "C" void kernel_launch(void* const* d_in, const int* in_sizes, int n_in,
                              void* d_out, int out_size)
{
    const float* x = nullptr; const float* w_qkv = nullptr;
    const float* w_out = nullptr; const float* b_out = nullptr;
    for (int i = 0; i < n_in; i++) {
        long n = in_sizes[i];
        if      (n == (long)MTOT * DD)     x     = (const float*)d_in[i];
        else if (n == 3L * DD * DD)        w_qkv = (const float*)d_in[i];
        else if (n == (long)DD * DD)       w_out = (const float*)d_in[i];
        else if (n == (long)DD)            b_out = (const float*)d_in[i];
    }
    float* out = (float*)d_out;

    float *qkv, *q, *k, *v, *ao;
    bf16 *xh, *xl, *wqh, *wql, *aoh, *aol, *woh, *wol;
    cudaGetSymbolAddress((void**)&qkv, g_qkv);
    cudaGetSymbolAddress((void**)&q,   g_q);
    cudaGetSymbolAddress((void**)&k,   g_k);
    cudaGetSymbolAddress((void**)&v,   g_v);
    cudaGetSymbolAddress((void**)&ao,  g_ao);
    cudaGetSymbolAddress((void**)&xh,  g_x_hi);
    cudaGetSymbolAddress((void**)&xl,  g_x_lo);
    cudaGetSymbolAddress((void**)&wqh, g_wq_hi);
    cudaGetSymbolAddress((void**)&wql, g_wq_lo);
    cudaGetSymbolAddress((void**)&aoh, g_ao_hi);
    cudaGetSymbolAddress((void**)&aol, g_ao_lo);
    cudaGetSymbolAddress((void**)&woh, g_wo_hi);
    cudaGetSymbolAddress((void**)&wol, g_wo_lo);

    // 0) split inputs to bf16 hi/lo
    {
        int n1 = MTOT * DD;
        split_kernel<<<(n1 + 255) / 256, 256>>>(x, xh, xl, n1);
        int n2 = 3 * DD * DD;
        split_kernel<<<(n2 + 255) / 256, 256>>>(w_qkv, wqh, wql, n2);
    }

    // 1) QKV projection (mma.sync 3-term): [4096,1024] @ [3072,1024]^T
    wgemm3_kernel<false><<<dim3((3 * DD) / 128, MTOT / 128), 256>>>(
        xh, xl, wqh, wql, nullptr, qkv, MTOT, 3 * DD, DD);

    // 2) RoPE + split/transpose
    {
        int total = BB * SS * HH * (DKH / 2);
        rope_split_kernel<<<(total + 255) / 256, 256>>>(qkv, q, k, v);
    }

    // 3) attention
    attn_kernel<<<dim3(SS / 64, BB * HH), 256>>>(q, k, v, ao);

    // 4) split attention output + w_out, then output projection + bias
    {
        int n1 = MTOT * DD;
        split_kernel<<<(n1 + 255) / 256, 256>>>(ao, aoh, aol, n1);
        int n2 = DD * DD;
        split_kernel<<<(n2 + 255) / 256, 256>>>(w_out, woh, wol, n2);
    }
    wgemm3_kernel<true><<<dim3(DD / 128, MTOT / 128), 256>>>(
        aoh, aol, woh, wol, b_out, out, MTOT, DD, DD);
}

// round 7
// speedup vs baseline: 2.7993x; 2.0957x over previous
#include <cuda_runtime.h>
#include <cuda_bf16.h>
#include <cstdint>
#include <math.h>

// Problem constants
#define BB   2
#define SS   2048
#define DD   1024
#define HH   16
#define DKH  64          // head dim
#define MTOT (BB*SS)     // 4096 rows

typedef __nv_bfloat16 bf16;

// -------- scratch (static device globals; allocation-free) --------
__device__ float g_qkv[(size_t)MTOT * 3 * DD];        // [4096, 3072]
__device__ float g_ao [(size_t)MTOT * DD];            // attention out, [b,s,h*d]
__device__ float2 g_trig[SS * 32];                    // cos/sin table [s][p]

__device__ bf16 g_x_hi [(size_t)MTOT * DD];
__device__ bf16 g_x_lo [(size_t)MTOT * DD];
__device__ bf16 g_wq_hi[(size_t)3 * DD * DD];
__device__ bf16 g_wq_lo[(size_t)3 * DD * DD];
__device__ bf16 g_ao_hi[(size_t)MTOT * DD];
__device__ bf16 g_ao_lo[(size_t)MTOT * DD];
__device__ bf16 g_wo_hi[(size_t)DD * DD];
__device__ bf16 g_wo_lo[(size_t)DD * DD];

// attention operands, bf16 hi/lo
__device__ bf16 g_qh[(size_t)BB * HH * SS * DKH];   // [b,h,s,d]
__device__ bf16 g_ql[(size_t)BB * HH * SS * DKH];
__device__ bf16 g_kh[(size_t)BB * HH * SS * DKH];
__device__ bf16 g_kl[(size_t)BB * HH * SS * DKH];
__device__ bf16 g_vth[(size_t)BB * HH * DKH * SS];  // [b,h,d,s]  (V transposed)
__device__ bf16 g_vtl[(size_t)BB * HH * DKH * SS];

// ============================================================================
// warp mma.sync m16n8k16 bf16 (row.col), fp32 accumulate
// ============================================================================
__device__ __forceinline__ void mma16816(float* d,
                                         const uint32_t* a, const uint32_t* b) {
    asm volatile(
        "mma.sync.aligned.m16n8k16.row.col.f32.bf16.bf16.f32 "
        "{%0,%1,%2,%3}, {%4,%5,%6,%7}, {%8,%9}, {%0,%1,%2,%3};"
        : "+f"(d[0]), "+f"(d[1]), "+f"(d[2]), "+f"(d[3])
        : "r"(a[0]), "r"(a[1]), "r"(a[2]), "r"(a[3]), "r"(b[0]), "r"(b[1]));
}

// pack two f32 -> bf16x2 (lo = a, hi = b)
__device__ __forceinline__ uint32_t pack_bf2(float a, float b) {
    uint32_t r;
    asm("cvt.rn.bf16x2.f32 %0, %1, %2;" : "=r"(r) : "f"(b), "f"(a));
    return r;
}
__device__ __forceinline__ float lo_f(uint32_t p) { return __uint_as_float(p << 16); }
__device__ __forceinline__ float hi_f(uint32_t p) { return __uint_as_float(p & 0xffff0000u); }

// ============================================================================
// fp32 -> (hi, lo) bf16 split
// ============================================================================
__global__ void split_kernel(const float* __restrict__ src,
                             bf16* __restrict__ hi, bf16* __restrict__ lo, int n) {
    int i = blockIdx.x * blockDim.x + threadIdx.x;
    if (i >= n) return;
    float x = src[i];
    bf16 h = __float2bfloat16_rn(x);
    hi[i] = h;
    lo[i] = __float2bfloat16_rn(x - __bfloat162float(h));
}

// ============================================================================
// trig table: [s][p] cos/sin, accurate (double) evaluation of the fp32 angle
// ============================================================================
__global__ void trig_kernel(float2* __restrict__ T) {
    int idx = blockIdx.x * blockDim.x + threadIdx.x;
    if (idx >= SS * 32) return;
    int p = idx & 31, s = idx >> 5;
    float inv = 1.0f / powf(50.0f, (2.0f * (float)p) / 64.0f);
    float ang = (float)s * inv;          // fp32 rounding matches reference
    double sd, cd;
    sincos((double)ang, &sd, &cd);
    T[idx] = make_float2((float)cd, (float)sd);
}

// ============================================================================
// QK producer: rope + split to bf16 hi/lo, layout [b,h,s,64]
// ============================================================================
__global__ void qk_producer(const float* __restrict__ qkv,
                            const float2* __restrict__ T,
                            bf16* __restrict__ Qh, bf16* __restrict__ Ql,
                            bf16* __restrict__ Kh, bf16* __restrict__ Kl) {
    int idx = blockIdx.x * blockDim.x + threadIdx.x;   // ((b*S + s)*H + h)*32 + p
    if (idx >= BB * SS * HH * 32) return;
    int p = idx & 31;
    int h = (idx >> 5) & (HH - 1);
    int s = (idx >> 9) & (SS - 1);
    int b = idx >> 20;

    float2 cs = T[s * 32 + p];
    const float* row = qkv + (size_t)(b * SS + s) * (3 * DD);
    int col = h * DKH + 2 * p;

    float q0 = row[col],      q1 = row[col + 1];
    float k0 = row[DD + col], k1 = row[DD + col + 1];

    float qr0 = q0 * cs.x - q1 * cs.y;
    float qr1 = q1 * cs.x + q0 * cs.y;
    float kr0 = k0 * cs.x - k1 * cs.y;
    float kr1 = k1 * cs.x + k0 * cs.y;

    size_t o = ((size_t)(b * HH + h) * SS + s) * DKH + 2 * p;
    bf16 a, c;
    a = __float2bfloat16_rn(qr0); Qh[o] = a; Ql[o] = __float2bfloat16_rn(qr0 - __bfloat162float(a));
    c = __float2bfloat16_rn(qr1); Qh[o+1] = c; Ql[o+1] = __float2bfloat16_rn(qr1 - __bfloat162float(c));
    a = __float2bfloat16_rn(kr0); Kh[o] = a; Kl[o] = __float2bfloat16_rn(kr0 - __bfloat162float(a));
    c = __float2bfloat16_rn(kr1); Kh[o+1] = c; Kl[o+1] = __float2bfloat16_rn(kr1 - __bfloat162float(c));
}

// ============================================================================
// V producer: transpose to [b,h,d,s] + split bf16 hi/lo via smem tile
// grid (S/64, H, B), 256 threads
// Read phase: 1024 items (64 rows x 16 float4 chunks) -> 4 iterations.
// Write phase: 256 items (64 d-rows x 4 s-chunks)     -> exactly ONE per thread.
// ============================================================================
__global__ __launch_bounds__(256) void v_producer(const float* __restrict__ qkv,
                                                  bf16* __restrict__ Vth,
                                                  bf16* __restrict__ Vtl) {
    __shared__ float sV[64][65];
    const int st = blockIdx.x, h = blockIdx.y, b = blockIdx.z;
    const int tid = threadIdx.x;

    // read 64 s-rows x 64 dk floats (each row = 16 float4)
    #pragma unroll
    for (int i = 0; i < 4; i++) {
        int idx = tid + i * 256;
        int r = idx >> 4, c = idx & 15;
        const float4 v = *(const float4*)(qkv + (size_t)(b * SS + st * 64 + r) * (3 * DD)
                                          + 2 * DD + h * DKH + c * 4);
        sV[r][c * 4 + 0] = v.x; sV[r][c * 4 + 1] = v.y;
        sV[r][c * 4 + 2] = v.z; sV[r][c * 4 + 3] = v.w;
    }
    __syncthreads();

    // write transposed: each thread handles one (d, 16-s chunk): 256 items total
    {
        int d  = tid >> 2;         // 0..63
        int ch = tid & 3;          // 0..3
        bf16 hbuf[16], lbuf[16];
        #pragma unroll
        for (int s = 0; s < 16; s++) {
            float v = sV[ch * 16 + s][d];
            bf16 hv = __float2bfloat16_rn(v);
            hbuf[s] = hv;
            lbuf[s] = __float2bfloat16_rn(v - __bfloat162float(hv));
        }
        size_t o = ((size_t)(b * HH + h) * DKH + d) * SS + st * 64 + ch * 16;
        *(uint4*)(Vth + o)     = *(uint4*)hbuf;
        *(uint4*)(Vth + o + 8) = *(uint4*)(hbuf + 8);
        *(uint4*)(Vtl + o)     = *(uint4*)lbuf;
        *(uint4*)(Vtl + o + 8) = *(uint4*)(lbuf + 8);
    }
}

// ============================================================================
// Tensor-core flash attention with split-bf16 precision.
// Grid (S/128, B*H), 256 threads = 8 warps, each warp owns 16 query rows.
// ============================================================================
#define AST 72   // smem row stride in bf16 (144B)

__global__ __launch_bounds__(256) void attn_mma(
    const bf16* __restrict__ Qh, const bf16* __restrict__ Ql,
    const bf16* __restrict__ Kh, const bf16* __restrict__ Kl,
    const bf16* __restrict__ Vth, const bf16* __restrict__ Vtl,
    float* __restrict__ O)
{
    __shared__ bf16 sKh[64 * AST];
    __shared__ bf16 sKl[64 * AST];
    __shared__ bf16 sVh[64 * AST];   // Vt: [dk][key]
    __shared__ bf16 sVl[64 * AST];

    const int tid  = threadIdx.x;
    const int wid  = tid >> 5;
    const int lane = tid & 31;
    const int g    = lane >> 2;       // 0..7
    const int t4   = lane & 3;        // 0..3

    const int bh = blockIdx.y;
    const int b  = bh >> 4;
    const int h  = bh & 15;
    const int q0 = blockIdx.x * 128 + wid * 16;   // warp's first query row

    // ---- load Q fragments (hi & lo), A-frag layout ----
    const bf16* Qbh = Qh + ((size_t)bh * SS + q0) * DKH;
    const bf16* Qbl = Ql + ((size_t)bh * SS + q0) * DKH;
    uint32_t qh[4][4], ql[4][4];
    #pragma unroll
    for (int ks = 0; ks < 4; ks++) {
        const int c0 = ks * 16 + 2 * t4;
        qh[ks][0] = *(const uint32_t*)(Qbh + (size_t)g * DKH + c0);
        qh[ks][1] = *(const uint32_t*)(Qbh + (size_t)(g + 8) * DKH + c0);
        qh[ks][2] = *(const uint32_t*)(Qbh + (size_t)g * DKH + c0 + 8);
        qh[ks][3] = *(const uint32_t*)(Qbh + (size_t)(g + 8) * DKH + c0 + 8);
        ql[ks][0] = *(const uint32_t*)(Qbl + (size_t)g * DKH + c0);
        ql[ks][1] = *(const uint32_t*)(Qbl + (size_t)(g + 8) * DKH + c0);
        ql[ks][2] = *(const uint32_t*)(Qbl + (size_t)g * DKH + c0 + 8);
        ql[ks][3] = *(const uint32_t*)(Qbl + (size_t)(g + 8) * DKH + c0 + 8);
    }

    float m0 = -1e30f, m1 = -1e30f, l0 = 0.f, l1 = 0.f;
    float acc[8][4];
    #pragma unroll
    for (int n = 0; n < 8; n++)
        #pragma unroll
        for (int r = 0; r < 4; r++) acc[n][r] = 0.f;

    const float SC2 = 0.125f * 1.44269504088896340736f;   // scale * log2(e)
    const int rg  = q0 + g;          // global query rows for this lane
    const int rg8 = rg + 8;

    const bf16* Kbh = Kh + (size_t)bh * SS * DKH;
    const bf16* Kbl = Kl + (size_t)bh * SS * DKH;
    const bf16* Vbh = Vth + (size_t)bh * DKH * SS;
    const bf16* Vbl = Vtl + (size_t)bh * DKH * SS;

    for (int t = 0; t < SS / 64; ++t) {
        // ---- load K (hi/lo) [64key][64dk] and Vt (hi/lo) [64dk][64key] ----
        #pragma unroll
        for (int rep = 0; rep < 2; rep++) {
            int idx = tid + rep * 256;      // 0..511
            int row = idx >> 3, ch = idx & 7;
            size_t sk = (size_t)(t * 64 + row) * DKH + ch * 8;
            *(uint4*)(sKh + row * AST + ch * 8) = *(const uint4*)(Kbh + sk);
            *(uint4*)(sKl + row * AST + ch * 8) = *(const uint4*)(Kbl + sk);
            size_t sv = (size_t)row * SS + t * 64 + ch * 8;
            *(uint4*)(sVh + row * AST + ch * 8) = *(const uint4*)(Vbh + sv);
            *(uint4*)(sVl + row * AST + ch * 8) = *(const uint4*)(Vbl + sv);
        }
        __syncthreads();

        // ---- S = Q K^T (3-term), 8 n-tiles of 8 keys ----
        float S[8][4];
        #pragma unroll
        for (int j = 0; j < 8; j++) {
            S[j][0] = S[j][1] = S[j][2] = S[j][3] = 0.f;
            #pragma unroll
            for (int ks = 0; ks < 4; ks++) {
                const int ko = ks * 16 + 2 * t4;
                uint32_t bhfr[2], blfr[2];
                bhfr[0] = *(const uint32_t*)(sKh + (8 * j + g) * AST + ko);
                bhfr[1] = *(const uint32_t*)(sKh + (8 * j + g) * AST + ko + 8);
                blfr[0] = *(const uint32_t*)(sKl + (8 * j + g) * AST + ko);
                blfr[1] = *(const uint32_t*)(sKl + (8 * j + g) * AST + ko + 8);
                mma16816(S[j], qh[ks], bhfr);
                mma16816(S[j], ql[ks], bhfr);
                mma16816(S[j], qh[ks], blfr);
            }
        }

        // ---- scale to base-2, diagonal mask ----
        float rm0 = -1e30f, rm1 = -1e30f;
        #pragma unroll
        for (int j = 0; j < 8; j++) {
            int k0i = t * 64 + 8 * j + 2 * t4;
            S[j][0] = (k0i     == rg ) ? -1e30f : S[j][0] * SC2;
            S[j][1] = (k0i + 1 == rg ) ? -1e30f : S[j][1] * SC2;
            S[j][2] = (k0i     == rg8) ? -1e30f : S[j][2] * SC2;
            S[j][3] = (k0i + 1 == rg8) ? -1e30f : S[j][3] * SC2;
            rm0 = fmaxf(rm0, fmaxf(S[j][0], S[j][1]));
            rm1 = fmaxf(rm1, fmaxf(S[j][2], S[j][3]));
        }
        rm0 = fmaxf(rm0, __shfl_xor_sync(0xffffffffu, rm0, 1));
        rm0 = fmaxf(rm0, __shfl_xor_sync(0xffffffffu, rm0, 2));
        rm1 = fmaxf(rm1, __shfl_xor_sync(0xffffffffu, rm1, 1));
        rm1 = fmaxf(rm1, __shfl_xor_sync(0xffffffffu, rm1, 2));

        float mn0 = fmaxf(m0, rm0), mn1 = fmaxf(m1, rm1);
        float corr0 = exp2f(m0 - mn0), corr1 = exp2f(m1 - mn1);
        m0 = mn0; m1 = mn1;

        float rs0 = 0.f, rs1 = 0.f;
        #pragma unroll
        for (int j = 0; j < 8; j++) {
            S[j][0] = exp2f(S[j][0] - mn0);
            S[j][1] = exp2f(S[j][1] - mn0);
            S[j][2] = exp2f(S[j][2] - mn1);
            S[j][3] = exp2f(S[j][3] - mn1);
            rs0 += S[j][0] + S[j][1];
            rs1 += S[j][2] + S[j][3];
        }
        rs0 += __shfl_xor_sync(0xffffffffu, rs0, 1);
        rs0 += __shfl_xor_sync(0xffffffffu, rs0, 2);
        rs1 += __shfl_xor_sync(0xffffffffu, rs1, 1);
        rs1 += __shfl_xor_sync(0xffffffffu, rs1, 2);
        l0 = l0 * corr0 + rs0;
        l1 = l1 * corr1 + rs1;

        #pragma unroll
        for (int n = 0; n < 8; n++) {
            acc[n][0] *= corr0; acc[n][1] *= corr0;
            acc[n][2] *= corr1; acc[n][3] *= corr1;
        }

        // ---- pack P hi/lo into A-fragments (k-steps of 16 keys) ----
        uint32_t ph[4][4], pl[4][4];
        #pragma unroll
        for (int q = 0; q < 4; q++) {
            const int j0 = 2 * q, j1 = 2 * q + 1;
            ph[q][0] = pack_bf2(S[j0][0], S[j0][1]);
            ph[q][1] = pack_bf2(S[j0][2], S[j0][3]);
            ph[q][2] = pack_bf2(S[j1][0], S[j1][1]);
            ph[q][3] = pack_bf2(S[j1][2], S[j1][3]);
            pl[q][0] = pack_bf2(S[j0][0] - lo_f(ph[q][0]), S[j0][1] - hi_f(ph[q][0]));
            pl[q][1] = pack_bf2(S[j0][2] - lo_f(ph[q][1]), S[j0][3] - hi_f(ph[q][1]));
            pl[q][2] = pack_bf2(S[j1][0] - lo_f(ph[q][2]), S[j1][1] - hi_f(ph[q][2]));
            pl[q][3] = pack_bf2(S[j1][2] - lo_f(ph[q][3]), S[j1][3] - hi_f(ph[q][3]));
        }

        // ---- O += P V (3-term): 8 dk n-tiles x 4 k-steps ----
        #pragma unroll
        for (int n = 0; n < 8; n++) {
            #pragma unroll
            for (int q = 0; q < 4; q++) {
                const int ko = q * 16 + 2 * t4;
                uint32_t vh[2], vl[2];
                vh[0] = *(const uint32_t*)(sVh + (8 * n + g) * AST + ko);
                vh[1] = *(const uint32_t*)(sVh + (8 * n + g) * AST + ko + 8);
                vl[0] = *(const uint32_t*)(sVl + (8 * n + g) * AST + ko);
                vl[1] = *(const uint32_t*)(sVl + (8 * n + g) * AST + ko + 8);
                mma16816(acc[n], ph[q], vh);
                mma16816(acc[n], pl[q], vh);
                mma16816(acc[n], ph[q], vl);
            }
        }
        __syncthreads();
    }

    // ---- epilogue: normalize, write [b, s, h*64 + dk] ----
    const float inv0 = 1.0f / l0, inv1 = 1.0f / l1;
    float* O0 = O + ((size_t)(b * SS + rg )) * DD + h * DKH;
    float* O1 = O + ((size_t)(b * SS + rg8)) * DD + h * DKH;
    #pragma unroll
    for (int n = 0; n < 8; n++) {
        const int c = 8 * n + 2 * t4;
        O0[c]     = acc[n][0] * inv0;
        O0[c + 1] = acc[n][1] * inv0;
        O1[c]     = acc[n][2] * inv1;
        O1[c + 1] = acc[n][3] * inv1;
    }
}

// ============================================================================
// 3-term split-bf16 GEMM via mma.sync (unchanged from R4, verified)
// ============================================================================
#define GST 40   // smem row stride in bf16 elements

template<bool HAS_BIAS>
__global__ __launch_bounds__(256)
void wgemm3_kernel(const bf16* __restrict__ Ahi, const bf16* __restrict__ Alo,
                   const bf16* __restrict__ Bhi, const bf16* __restrict__ Blo,
                   const float* __restrict__ bias, float* __restrict__ C,
                   int M, int N, int K)
{
    __shared__ bf16 sAh[128][GST];
    __shared__ bf16 sAl[128][GST];
    __shared__ bf16 sBh[128][GST];
    __shared__ bf16 sBl[128][GST];

    const int tid  = threadIdx.x;
    const int wid  = tid >> 5;
    const int lane = tid & 31;
    const int lr   = lane >> 2;
    const int lc   = (lane & 3) * 2;

    const int mbase = blockIdx.y * 128;
    const int nbase = blockIdx.x * 128;
    const int wm = (wid >> 2) * 64;
    const int wn = (wid & 3) * 32;

    float acc[4][4][4];
    #pragma unroll
    for (int mi = 0; mi < 4; mi++)
        #pragma unroll
        for (int ni = 0; ni < 4; ni++)
            #pragma unroll
            for (int r = 0; r < 4; r++) acc[mi][ni][r] = 0.f;

    for (int k0 = 0; k0 < K; k0 += 32) {
        #pragma unroll
        for (int it = 0; it < 2; it++) {
            int idx = tid + it * 256;
            int row = idx >> 2;
            int c4  = idx & 3;
            size_t sa = (size_t)(mbase + row) * K + k0 + c4 * 8;
            size_t sb = (size_t)(nbase + row) * K + k0 + c4 * 8;
            *(uint4*)&sAh[row][c4 * 8] = *(const uint4*)(Ahi + sa);
            *(uint4*)&sAl[row][c4 * 8] = *(const uint4*)(Alo + sa);
            *(uint4*)&sBh[row][c4 * 8] = *(const uint4*)(Bhi + sb);
            *(uint4*)&sBl[row][c4 * 8] = *(const uint4*)(Blo + sb);
        }
        __syncthreads();

        #pragma unroll
        for (int ks = 0; ks < 32; ks += 16) {
            uint32_t ah[4][4], al[4][4];
            #pragma unroll
            for (int mi = 0; mi < 4; mi++) {
                int r0 = wm + mi * 16 + lr;
                ah[mi][0] = *(const uint32_t*)&sAh[r0    ][ks + lc];
                ah[mi][1] = *(const uint32_t*)&sAh[r0 + 8][ks + lc];
                ah[mi][2] = *(const uint32_t*)&sAh[r0    ][ks + 8 + lc];
                ah[mi][3] = *(const uint32_t*)&sAh[r0 + 8][ks + 8 + lc];
                al[mi][0] = *(const uint32_t*)&sAl[r0    ][ks + lc];
                al[mi][1] = *(const uint32_t*)&sAl[r0 + 8][ks + lc];
                al[mi][2] = *(const uint32_t*)&sAl[r0    ][ks + 8 + lc];
                al[mi][3] = *(const uint32_t*)&sAl[r0 + 8][ks + 8 + lc];
            }
            uint32_t bh[4][2], bl[4][2];
            #pragma unroll
            for (int ni = 0; ni < 4; ni++) {
                int rn = wn + ni * 8 + lr;
                bh[ni][0] = *(const uint32_t*)&sBh[rn][ks + lc];
                bh[ni][1] = *(const uint32_t*)&sBh[rn][ks + 8 + lc];
                bl[ni][0] = *(const uint32_t*)&sBl[rn][ks + lc];
                bl[ni][1] = *(const uint32_t*)&sBl[rn][ks + 8 + lc];
            }
            #pragma unroll
            for (int mi = 0; mi < 4; mi++)
                #pragma unroll
                for (int ni = 0; ni < 4; ni++) {
                    mma16816(acc[mi][ni], ah[mi], bh[ni]);
                    mma16816(acc[mi][ni], al[mi], bh[ni]);
                    mma16816(acc[mi][ni], ah[mi], bl[ni]);
                }
        }
        __syncthreads();
    }

    #pragma unroll
    for (int mi = 0; mi < 4; mi++) {
        int row0 = mbase + wm + mi * 16 + lr;
        #pragma unroll
        for (int ni = 0; ni < 4; ni++) {
            int col0 = nbase + wn + ni * 8 + lc;
            float b0 = 0.f, b1 = 0.f;
            if (HAS_BIAS) { b0 = bias[col0]; b1 = bias[col0 + 1]; }
            float* p0 = C + (size_t)row0 * N + col0;
            float* p1 = C + (size_t)(row0 + 8) * N + col0;
            p0[0] = acc[mi][ni][0] + b0;
            p0[1] = acc[mi][ni][1] + b1;
            p1[0] = acc[mi][ni][2] + b0;
            p1[1] = acc[mi][ni][3] + b1;
        }
    }
}

// ============================================================================
// launch
// ============================================================================
extern "C" void kernel_launch(void* const* d_in, const int* in_sizes, int n_in,
                              void* d_out, int out_size)
{
    const float* x = nullptr; const float* w_qkv = nullptr;
    const float* w_out = nullptr; const float* b_out = nullptr;
    for (int i = 0; i < n_in; i++) {
        long n = in_sizes[i];
        if      (n == (long)MTOT * DD)     x     = (const float*)d_in[i];
        else if (n == 3L * DD * DD)        w_qkv = (const float*)d_in[i];
        else if (n == (long)DD * DD)       w_out = (const float*)d_in[i];
        else if (n == (long)DD)            b_out = (const float*)d_in[i];
    }
    float* out = (float*)d_out;

    float *qkv, *ao; float2* trig;
    bf16 *xh, *xl, *wqh, *wql, *aoh, *aol, *woh, *wol;
    bf16 *qhp, *qlp, *khp, *klp, *vth, *vtl;
    cudaGetSymbolAddress((void**)&qkv, g_qkv);
    cudaGetSymbolAddress((void**)&ao,  g_ao);
    cudaGetSymbolAddress((void**)&trig, g_trig);
    cudaGetSymbolAddress((void**)&xh,  g_x_hi);
    cudaGetSymbolAddress((void**)&xl,  g_x_lo);
    cudaGetSymbolAddress((void**)&wqh, g_wq_hi);
    cudaGetSymbolAddress((void**)&wql, g_wq_lo);
    cudaGetSymbolAddress((void**)&aoh, g_ao_hi);
    cudaGetSymbolAddress((void**)&aol, g_ao_lo);
    cudaGetSymbolAddress((void**)&woh, g_wo_hi);
    cudaGetSymbolAddress((void**)&wol, g_wo_lo);
    cudaGetSymbolAddress((void**)&qhp, g_qh);
    cudaGetSymbolAddress((void**)&qlp, g_ql);
    cudaGetSymbolAddress((void**)&khp, g_kh);
    cudaGetSymbolAddress((void**)&klp, g_kl);
    cudaGetSymbolAddress((void**)&vth, g_vth);
    cudaGetSymbolAddress((void**)&vtl, g_vtl);

    // 0) split inputs to bf16 hi/lo, trig table
    {
        int n1 = MTOT * DD;
        split_kernel<<<(n1 + 255) / 256, 256>>>(x, xh, xl, n1);
        int n2 = 3 * DD * DD;
        split_kernel<<<(n2 + 255) / 256, 256>>>(w_qkv, wqh, wql, n2);
        trig_kernel<<<(SS * 32 + 255) / 256, 256>>>(trig);
        int n3 = DD * DD;
        split_kernel<<<(n3 + 255) / 256, 256>>>(w_out, woh, wol, n3);
    }

    // 1) QKV projection (mma.sync 3-term)
    wgemm3_kernel<false><<<dim3((3 * DD) / 128, MTOT / 128), 256>>>(
        xh, xl, wqh, wql, nullptr, qkv, MTOT, 3 * DD, DD);

    // 2) producers: rope+split Q/K, transpose+split V
    {
        int total = BB * SS * HH * 32;
        qk_producer<<<(total + 255) / 256, 256>>>(qkv, trig, qhp, qlp, khp, klp);
        v_producer<<<dim3(SS / 64, HH, BB), 256>>>(qkv, vth, vtl);
    }

    // 3) tensor-core attention
    attn_mma<<<dim3(SS / 128, BB * HH), 256>>>(qhp, qlp, khp, klp, vth, vtl, ao);

    // 4) split attention output, output projection + bias
    {
        int n1 = MTOT * DD;
        split_kernel<<<(n1 + 255) / 256, 256>>>(ao, aoh, aol, n1);
    }
    wgemm3_kernel<true><<<dim3(DD / 128, MTOT / 128), 256>>>(
        aoh, aol, woh, wol, b_out, out, MTOT, DD, DD);
}